// round 14
// baseline (speedup 1.0000x reference)
#include <cuda_runtime.h>
#include <math.h>

#define W 16384
#define NB 4
#define NCH 128
#define NSKIP 256
#define LAYERS 30
#define TT 128

// ---------------- scratch (device globals; no allocation allowed) ----------------
__device__ float g_h[NB * NCH * W];          // residual stream (32 MB)
__device__ float g_gated[NB * NCH * W];      // GLU output per layer (32 MB)
__device__ float g_skips[NB * NSKIP * W];    // skip accumulator (64 MB)
__device__ float g_z[NB * NSKIP * W];        // post-a activations (64 MB)
__device__ float g_Aconv[LAYERS * 256 * 256]; // K-major conv weights [l][k][o]
__device__ float g_Ares[LAYERS * 128 * 128];  // K-major res weights  [l][k][o]
__device__ float g_Askip[LAYERS * 128 * 256]; // K-major skip weights [l][k][o]
__device__ float g_Aa[256 * 256];             // K-major a_w [k][o]
__device__ float g_Ab[256 * 256];             // K-major b_w [k][o]

// ---------------- weight prep (transpose to K-major for coalesced smem staging) ----
__global__ void prep_conv_kernel(const float* __restrict__ conv_w) {
    int idx = blockIdx.x * blockDim.x + threadIdx.x;
    if (idx >= LAYERS * 256 * 256) return;
    int o = idx & 255;
    int k = (idx >> 8) & 255;
    int l = idx >> 16;
    int c = k & 127;      // channel
    int j = k >> 7;       // tap: 0 -> t-d, 1 -> t
    g_Aconv[idx] = conv_w[((l * 256 + o) * 128 + c) * 2 + j];
}

__global__ void prep_res_kernel(const float* __restrict__ res_w) {
    int idx = blockIdx.x * blockDim.x + threadIdx.x;
    if (idx >= LAYERS * 128 * 128) return;
    int o = idx & 127;
    int k = (idx >> 7) & 127;
    int l = idx >> 14;
    g_Ares[idx] = res_w[(l * 128 + o) * 128 + k];
}

__global__ void prep_skip_kernel(const float* __restrict__ skip_w) {
    int idx = blockIdx.x * blockDim.x + threadIdx.x;
    if (idx >= LAYERS * 128 * 256) return;
    int o = idx & 255;
    int k = (idx >> 8) & 127;
    int l = idx >> 15;
    g_Askip[idx] = skip_w[(l * 256 + o) * 128 + k];
}

__global__ void prep_ab_kernel(const float* __restrict__ a_w, const float* __restrict__ b_w) {
    int idx = blockIdx.x * blockDim.x + threadIdx.x;
    if (idx >= 256 * 256) return;
    int o = idx & 255;
    int k = idx >> 8;
    g_Aa[idx] = a_w[o * 256 + k];
    g_Ab[idx] = b_w[o * 256 + k];
}

// ---------------- front: shift-by-1 then causal conv k=2 d=1 ----------------------
// h[n,c,t] = w[c,0]*x[n,t-2] + w[c,1]*x[n,t-1] + b[c]
__global__ void front_kernel(const float* __restrict__ x,
                             const float* __restrict__ w_shift,
                             const float* __restrict__ b_shift) {
    int idx = blockIdx.x * blockDim.x + threadIdx.x;
    if (idx >= NB * NCH * W) return;
    int t = idx & (W - 1);
    int c = (idx >> 14) & 127;
    int n = idx >> 21;
    float xm2 = (t >= 2) ? x[n * W + t - 2] : 0.f;
    float xm1 = (t >= 1) ? x[n * W + t - 1] : 0.f;
    g_h[idx] = w_shift[c * 2] * xm2 + w_shift[c * 2 + 1] * xm1 + b_shift[c];
}

// ---------------- per-layer dilated conv + GLU (fused) ----------------------------
// pre[o,t] = sum_c W0[o,c]*h[c,t-d] + W1[o,c]*h[c,t] + bias[o]   (o in 0..255)
// gated[r,t] = pre[r,t] * sigmoid(pre[r+128,t])                  (r in 0..127)
// Block: full M=256, time tile TT=128, K=256 (virtual: k<128 tap0, k>=128 tap1).
// 512 threads; thread owns rows {r0..r0+3, r0+128..r0+131} x 8 time cols,
// so the GLU pairing stays in-register.
__global__ __launch_bounds__(512, 1) void conv_glu_kernel(
    const float* __restrict__ At,    // [256][256] K-major for this layer
    const float* __restrict__ bias,  // [256]
    int d) {
    __shared__ __align__(16) float As[8][256];
    __shared__ __align__(16) float Bs[8][TT];

    int n = blockIdx.z;
    int t0 = blockIdx.x * TT;
    const float* hb = g_h + (size_t)n * NCH * W;

    int tid = threadIdx.x;
    int mg = tid >> 4;     // 0..31
    int tg = tid & 15;     // 0..15
    int r0 = mg * 4;       // a-rows r0..r0+3, b-rows r0+128..r0+131
    int tl = tg * 8;

    float acc[8][8];
#pragma unroll
    for (int i = 0; i < 8; i++)
#pragma unroll
        for (int j = 0; j < 8; j++) acc[i][j] = 0.f;

    for (int k0 = 0; k0 < 256; k0 += 8) {
        // A tile: 8x256, 4 floats/thread, coalesced (K-major layout)
        {
            int e = tid * 4;
            int kr = e >> 8;
            int col = e & 255;
            *(float4*)&As[kr][col] = *(const float4*)(At + (k0 + kr) * 256 + col);
        }
        // B tile: 8x128, 2 floats/thread. Row k<128 gathers h[.,t-d], k>=128 h[.,t].
        {
            int e = tid * 2;
            int kr = e >> 7;
            int col = e & 127;
            int kab = k0 + kr;
            int c = kab & 127;
            int ts = t0 + col - ((kab < 128) ? d : 0);
            const float* src = hb + (size_t)c * W;
            Bs[kr][col]     = (ts     >= 0) ? src[ts]     : 0.f;
            Bs[kr][col + 1] = (ts + 1 >= 0) ? src[ts + 1] : 0.f;
        }
        __syncthreads();
#pragma unroll
        for (int k = 0; k < 8; k++) {
            float4 a0 = *(float4*)&As[k][r0];
            float4 a1 = *(float4*)&As[k][128 + r0];
            float4 b0 = *(float4*)&Bs[k][tl];
            float4 b1 = *(float4*)&Bs[k][tl + 4];
            float av[4] = {a0.x, a0.y, a0.z, a0.w};
            float bw[4] = {a1.x, a1.y, a1.z, a1.w};
            float bj[8] = {b0.x, b0.y, b0.z, b0.w, b1.x, b1.y, b1.z, b1.w};
#pragma unroll
            for (int i = 0; i < 4; i++)
#pragma unroll
                for (int j = 0; j < 8; j++) {
                    acc[i][j]     += av[i] * bj[j];
                    acc[4 + i][j] += bw[i] * bj[j];
                }
        }
        __syncthreads();
    }

    float* gb = g_gated + (size_t)n * NCH * W;
#pragma unroll
    for (int i = 0; i < 4; i++) {
        float ba = bias[r0 + i];
        float bbv = bias[128 + r0 + i];
        float ov[8];
#pragma unroll
        for (int j = 0; j < 8; j++) {
            float a = acc[i][j] + ba;
            float b = acc[4 + i][j] + bbv;
            ov[j] = a * (1.f / (1.f + __expf(-b)));
        }
        float* dst = gb + (size_t)(r0 + i) * W + t0 + tl;
        *(float4*)dst       = make_float4(ov[0], ov[1], ov[2], ov[3]);
        *(float4*)(dst + 4) = make_float4(ov[4], ov[5], ov[6], ov[7]);
    }
}

// ---------------- generic 128x128-tile GEMM: C[m,t] (+)= sum_k At[k][m]*B[k,t] + bias[m]
template <bool ACC, bool RELUB, bool RELUOUT>
__global__ __launch_bounds__(256) void gemm_kernel(
    const float* __restrict__ At, int Mtot, int K,
    const float* __restrict__ bias,
    const float* __restrict__ B, float* __restrict__ C) {
    __shared__ __align__(16) float As[8][128];
    __shared__ __align__(16) float Bs[8][128];

    int n = blockIdx.z;
    int m0 = blockIdx.y * 128;
    int t0 = blockIdx.x * 128;
    const float* Bn = B + (size_t)n * K * W;
    float* Cn = C + (size_t)n * Mtot * W;

    int tid = threadIdx.x;
    int ty = tid >> 4;   // m-group
    int tx = tid & 15;   // t-group
    int ml = ty * 8;
    int tl = tx * 8;

    float acc[8][8];
#pragma unroll
    for (int i = 0; i < 8; i++)
#pragma unroll
        for (int j = 0; j < 8; j++) acc[i][j] = 0.f;

    for (int k0 = 0; k0 < K; k0 += 8) {
        int e = tid * 4;
        int kr = e >> 7;
        int col = e & 127;
        *(float4*)&As[kr][col] = *(const float4*)(At + (size_t)(k0 + kr) * Mtot + m0 + col);
        float4 bv = *(const float4*)(Bn + (size_t)(k0 + kr) * W + t0 + col);
        if (RELUB) {
            bv.x = fmaxf(bv.x, 0.f); bv.y = fmaxf(bv.y, 0.f);
            bv.z = fmaxf(bv.z, 0.f); bv.w = fmaxf(bv.w, 0.f);
        }
        *(float4*)&Bs[kr][col] = bv;
        __syncthreads();
#pragma unroll
        for (int k = 0; k < 8; k++) {
            float4 a0 = *(float4*)&As[k][ml];
            float4 a1 = *(float4*)&As[k][ml + 4];
            float4 b0 = *(float4*)&Bs[k][tl];
            float4 b1 = *(float4*)&Bs[k][tl + 4];
            float am[8] = {a0.x, a0.y, a0.z, a0.w, a1.x, a1.y, a1.z, a1.w};
            float bj[8] = {b0.x, b0.y, b0.z, b0.w, b1.x, b1.y, b1.z, b1.w};
#pragma unroll
            for (int i = 0; i < 8; i++)
#pragma unroll
                for (int j = 0; j < 8; j++) acc[i][j] += am[i] * bj[j];
        }
        __syncthreads();
    }

#pragma unroll
    for (int i = 0; i < 8; i++) {
        float bi = bias[m0 + ml + i];
        float* dst = Cn + (size_t)(m0 + ml + i) * W + t0 + tl;
#pragma unroll
        for (int g = 0; g < 2; g++) {
            float4 v;
            v.x = acc[i][g * 4 + 0] + bi;
            v.y = acc[i][g * 4 + 1] + bi;
            v.z = acc[i][g * 4 + 2] + bi;
            v.w = acc[i][g * 4 + 3] + bi;
            if (ACC) {
                float4 old = *(float4*)(dst + g * 4);
                v.x += old.x; v.y += old.y; v.z += old.z; v.w += old.w;
            }
            if (RELUOUT) {
                v.x = fmaxf(v.x, 0.f); v.y = fmaxf(v.y, 0.f);
                v.z = fmaxf(v.z, 0.f); v.w = fmaxf(v.w, 0.f);
            }
            *(float4*)(dst + g * 4) = v;
        }
    }
}

// ---------------- launch ----------------------------------------------------------
extern "C" void kernel_launch(void* const* d_in, const int* in_sizes, int n_in,
                              void* d_out, int out_size) {
    const float* x       = (const float*)d_in[0];
    const float* w_shift = (const float*)d_in[1];
    const float* b_shift = (const float*)d_in[2];
    const float* conv_w  = (const float*)d_in[3];
    const float* conv_b  = (const float*)d_in[4];
    const float* res_b   = (const float*)d_in[6];
    const float* skip_b  = (const float*)d_in[8];
    const float* a_b     = (const float*)d_in[10];
    const float* b_b     = (const float*)d_in[12];
    const float* res_w   = (const float*)d_in[5];
    const float* skip_w  = (const float*)d_in[7];
    const float* a_w     = (const float*)d_in[9];
    const float* b_w     = (const float*)d_in[11];
    float* out = (float*)d_out;

    float *p_h, *p_gated, *p_skips, *p_z, *p_Aconv, *p_Ares, *p_Askip, *p_Aa, *p_Ab;
    cudaGetSymbolAddress((void**)&p_h, g_h);
    cudaGetSymbolAddress((void**)&p_gated, g_gated);
    cudaGetSymbolAddress((void**)&p_skips, g_skips);
    cudaGetSymbolAddress((void**)&p_z, g_z);
    cudaGetSymbolAddress((void**)&p_Aconv, g_Aconv);
    cudaGetSymbolAddress((void**)&p_Ares, g_Ares);
    cudaGetSymbolAddress((void**)&p_Askip, g_Askip);
    cudaGetSymbolAddress((void**)&p_Aa, g_Aa);
    cudaGetSymbolAddress((void**)&p_Ab, g_Ab);

    // weight prep (cheap; every call to keep launch deterministic)
    prep_conv_kernel<<<(LAYERS * 256 * 256 + 255) / 256, 256>>>(conv_w);
    prep_res_kernel<<<(LAYERS * 128 * 128 + 255) / 256, 256>>>(res_w);
    prep_skip_kernel<<<(LAYERS * 128 * 256 + 255) / 256, 256>>>(skip_w);
    prep_ab_kernel<<<(256 * 256 + 255) / 256, 256>>>(a_w, b_w);

    front_kernel<<<(NB * NCH * W + 255) / 256, 256>>>(x, w_shift, b_shift);

    dim3 gconv(W / TT, 1, NB);
    dim3 gres(W / 128, 1, NB);
    dim3 gskip(W / 128, 2, NB);

    for (int l = 0; l < LAYERS; l++) {
        int d = 1 << (l % 10);
        conv_glu_kernel<<<gconv, 512>>>(p_Aconv + l * 256 * 256, conv_b + l * 256, d);
        // h += res_w @ gated + res_b
        gemm_kernel<true, false, false><<<gres, 256>>>(
            p_Ares + l * 128 * 128, 128, 128, res_b + l * 128, p_gated, p_h);
        // skips (+)= skip_w @ gated + skip_b   (layer 0 initializes)
        if (l == 0) {
            gemm_kernel<false, false, false><<<gskip, 256>>>(
                p_Askip, 256, 128, skip_b, p_gated, p_skips);
        } else {
            gemm_kernel<true, false, false><<<gskip, 256>>>(
                p_Askip + l * 128 * 256, 256, 128, skip_b + l * 256, p_gated, p_skips);
        }
    }

    // z = relu(a_w @ relu(skips) + a_b)
    gemm_kernel<false, true, true><<<gskip, 256>>>(p_Aa, 256, 256, a_b, p_skips, p_z);
    // out = b_w @ z + b_b
    gemm_kernel<false, false, false><<<gskip, 256>>>(p_Ab, 256, 256, b_b, p_z, out);

    (void)in_sizes; (void)n_in; (void)out_size;
}

// round 15
// speedup vs baseline: 1.0022x; 1.0022x over previous
#include <cuda_runtime.h>
#include <math.h>

#define W 16384
#define NB 4
#define NCH 128
#define NSKIP 256
#define LAYERS 30
#define TT 128

// ---------------- scratch (device globals; no allocation allowed) ----------------
__device__ float g_h[NB * NCH * W];          // residual stream (32 MB)
__device__ float g_gated[NB * NCH * W];      // GLU output per layer (32 MB)
__device__ float g_skips[NB * NSKIP * W];    // skip accumulator (64 MB)
__device__ float g_z[NB * NSKIP * W];        // post-a activations (64 MB)
__device__ float g_Aconv[LAYERS * 256 * 256]; // K-major conv weights [l][k][o]
__device__ float g_Ares[LAYERS * 128 * 128];  // K-major res weights  [l][k][o]
__device__ float g_Askip[LAYERS * 128 * 256]; // K-major skip weights [l][k][o]
__device__ float g_Aa[256 * 256];             // K-major a_w [k][o]
__device__ float g_Ab[256 * 256];             // K-major b_w [k][o]

// ---------------- weight prep (transpose to K-major for coalesced smem staging) ----
__global__ void prep_conv_kernel(const float* __restrict__ conv_w) {
    int idx = blockIdx.x * blockDim.x + threadIdx.x;
    if (idx >= LAYERS * 256 * 256) return;
    int o = idx & 255;
    int k = (idx >> 8) & 255;
    int l = idx >> 16;
    int c = k & 127;      // channel
    int j = k >> 7;       // tap: 0 -> t-d, 1 -> t
    g_Aconv[idx] = conv_w[((l * 256 + o) * 128 + c) * 2 + j];
}

__global__ void prep_res_kernel(const float* __restrict__ res_w) {
    int idx = blockIdx.x * blockDim.x + threadIdx.x;
    if (idx >= LAYERS * 128 * 128) return;
    int o = idx & 127;
    int k = (idx >> 7) & 127;
    int l = idx >> 14;
    g_Ares[idx] = res_w[(l * 128 + o) * 128 + k];
}

__global__ void prep_skip_kernel(const float* __restrict__ skip_w) {
    int idx = blockIdx.x * blockDim.x + threadIdx.x;
    if (idx >= LAYERS * 128 * 256) return;
    int o = idx & 255;
    int k = (idx >> 8) & 127;
    int l = idx >> 15;
    g_Askip[idx] = skip_w[(l * 256 + o) * 128 + k];
}

__global__ void prep_ab_kernel(const float* __restrict__ a_w, const float* __restrict__ b_w) {
    int idx = blockIdx.x * blockDim.x + threadIdx.x;
    if (idx >= 256 * 256) return;
    int o = idx & 255;
    int k = idx >> 8;
    g_Aa[idx] = a_w[o * 256 + k];
    g_Ab[idx] = b_w[o * 256 + k];
}

// ---------------- front: shift-by-1 then causal conv k=2 d=1 ----------------------
// h[n,c,t] = w[c,0]*x[n,t-2] + w[c,1]*x[n,t-1] + b[c]
__global__ void front_kernel(const float* __restrict__ x,
                             const float* __restrict__ w_shift,
                             const float* __restrict__ b_shift) {
    int idx = blockIdx.x * blockDim.x + threadIdx.x;
    if (idx >= NB * NCH * W) return;
    int t = idx & (W - 1);
    int c = (idx >> 14) & 127;
    int n = idx >> 21;
    float xm2 = (t >= 2) ? x[n * W + t - 2] : 0.f;
    float xm1 = (t >= 1) ? x[n * W + t - 1] : 0.f;
    g_h[idx] = w_shift[c * 2] * xm2 + w_shift[c * 2 + 1] * xm1 + b_shift[c];
}

// ---------------- per-layer dilated conv + GLU (fused) ----------------------------
// pre[o,t] = sum_c W0[o,c]*h[c,t-d] + W1[o,c]*h[c,t] + bias[o]   (o in 0..255)
// gated[r,t] = pre[r,t] * sigmoid(pre[r+128,t])                  (r in 0..127)
// Block: full M=256, time tile TT=128, K=256 (virtual: k<128 tap0, k>=128 tap1).
// 512 threads; thread owns rows {r0..r0+3, r0+128..r0+131} x 8 time cols,
// so the GLU pairing stays in-register.
__global__ __launch_bounds__(512, 1) void conv_glu_kernel(
    const float* __restrict__ At,    // [256][256] K-major for this layer
    const float* __restrict__ bias,  // [256]
    int d) {
    __shared__ __align__(16) float As[8][256];
    __shared__ __align__(16) float Bs[8][TT];

    int n = blockIdx.z;
    int t0 = blockIdx.x * TT;
    const float* hb = g_h + (size_t)n * NCH * W;

    int tid = threadIdx.x;
    int mg = tid >> 4;     // 0..31
    int tg = tid & 15;     // 0..15
    int r0 = mg * 4;       // a-rows r0..r0+3, b-rows r0+128..r0+131
    int tl = tg * 8;

    float acc[8][8];
#pragma unroll
    for (int i = 0; i < 8; i++)
#pragma unroll
        for (int j = 0; j < 8; j++) acc[i][j] = 0.f;

    for (int k0 = 0; k0 < 256; k0 += 8) {
        // A tile: 8x256, 4 floats/thread, coalesced (K-major layout)
        {
            int e = tid * 4;
            int kr = e >> 8;
            int col = e & 255;
            *(float4*)&As[kr][col] = *(const float4*)(At + (k0 + kr) * 256 + col);
        }
        // B tile: 8x128, 2 floats/thread. Row k<128 gathers h[.,t-d], k>=128 h[.,t].
        {
            int e = tid * 2;
            int kr = e >> 7;
            int col = e & 127;
            int kab = k0 + kr;
            int c = kab & 127;
            int ts = t0 + col - ((kab < 128) ? d : 0);
            const float* src = hb + (size_t)c * W;
            Bs[kr][col]     = (ts     >= 0) ? src[ts]     : 0.f;
            Bs[kr][col + 1] = (ts + 1 >= 0) ? src[ts + 1] : 0.f;
        }
        __syncthreads();
#pragma unroll
        for (int k = 0; k < 8; k++) {
            float4 a0 = *(float4*)&As[k][r0];
            float4 a1 = *(float4*)&As[k][128 + r0];
            float4 b0 = *(float4*)&Bs[k][tl];
            float4 b1 = *(float4*)&Bs[k][tl + 4];
            float av[4] = {a0.x, a0.y, a0.z, a0.w};
            float bw[4] = {a1.x, a1.y, a1.z, a1.w};
            float bj[8] = {b0.x, b0.y, b0.z, b0.w, b1.x, b1.y, b1.z, b1.w};
#pragma unroll
            for (int i = 0; i < 4; i++)
#pragma unroll
                for (int j = 0; j < 8; j++) {
                    acc[i][j]     += av[i] * bj[j];
                    acc[4 + i][j] += bw[i] * bj[j];
                }
        }
        __syncthreads();
    }

    float* gb = g_gated + (size_t)n * NCH * W;
#pragma unroll
    for (int i = 0; i < 4; i++) {
        float ba = bias[r0 + i];
        float bbv = bias[128 + r0 + i];
        float ov[8];
#pragma unroll
        for (int j = 0; j < 8; j++) {
            float a = acc[i][j] + ba;
            float b = acc[4 + i][j] + bbv;
            ov[j] = a * (1.f / (1.f + __expf(-b)));
        }
        float* dst = gb + (size_t)(r0 + i) * W + t0 + tl;
        *(float4*)dst       = make_float4(ov[0], ov[1], ov[2], ov[3]);
        *(float4*)(dst + 4) = make_float4(ov[4], ov[5], ov[6], ov[7]);
    }
}

// ---------------- generic 128x128-tile GEMM: C[m,t] (+)= sum_k At[k][m]*B[k,t] + bias[m]
template <bool ACC, bool RELUB, bool RELUOUT>
__global__ __launch_bounds__(256) void gemm_kernel(
    const float* __restrict__ At, int Mtot, int K,
    const float* __restrict__ bias,
    const float* __restrict__ B, float* __restrict__ C) {
    __shared__ __align__(16) float As[8][128];
    __shared__ __align__(16) float Bs[8][128];

    int n = blockIdx.z;
    int m0 = blockIdx.y * 128;
    int t0 = blockIdx.x * 128;
    const float* Bn = B + (size_t)n * K * W;
    float* Cn = C + (size_t)n * Mtot * W;

    int tid = threadIdx.x;
    int ty = tid >> 4;   // m-group
    int tx = tid & 15;   // t-group
    int ml = ty * 8;
    int tl = tx * 8;

    float acc[8][8];
#pragma unroll
    for (int i = 0; i < 8; i++)
#pragma unroll
        for (int j = 0; j < 8; j++) acc[i][j] = 0.f;

    for (int k0 = 0; k0 < K; k0 += 8) {
        int e = tid * 4;
        int kr = e >> 7;
        int col = e & 127;
        *(float4*)&As[kr][col] = *(const float4*)(At + (size_t)(k0 + kr) * Mtot + m0 + col);
        float4 bv = *(const float4*)(Bn + (size_t)(k0 + kr) * W + t0 + col);
        if (RELUB) {
            bv.x = fmaxf(bv.x, 0.f); bv.y = fmaxf(bv.y, 0.f);
            bv.z = fmaxf(bv.z, 0.f); bv.w = fmaxf(bv.w, 0.f);
        }
        *(float4*)&Bs[kr][col] = bv;
        __syncthreads();
#pragma unroll
        for (int k = 0; k < 8; k++) {
            float4 a0 = *(float4*)&As[k][ml];
            float4 a1 = *(float4*)&As[k][ml + 4];
            float4 b0 = *(float4*)&Bs[k][tl];
            float4 b1 = *(float4*)&Bs[k][tl + 4];
            float am[8] = {a0.x, a0.y, a0.z, a0.w, a1.x, a1.y, a1.z, a1.w};
            float bj[8] = {b0.x, b0.y, b0.z, b0.w, b1.x, b1.y, b1.z, b1.w};
#pragma unroll
            for (int i = 0; i < 8; i++)
#pragma unroll
                for (int j = 0; j < 8; j++) acc[i][j] += am[i] * bj[j];
        }
        __syncthreads();
    }

#pragma unroll
    for (int i = 0; i < 8; i++) {
        float bi = bias[m0 + ml + i];
        float* dst = Cn + (size_t)(m0 + ml + i) * W + t0 + tl;
#pragma unroll
        for (int g = 0; g < 2; g++) {
            float4 v;
            v.x = acc[i][g * 4 + 0] + bi;
            v.y = acc[i][g * 4 + 1] + bi;
            v.z = acc[i][g * 4 + 2] + bi;
            v.w = acc[i][g * 4 + 3] + bi;
            if (ACC) {
                float4 old = *(float4*)(dst + g * 4);
                v.x += old.x; v.y += old.y; v.z += old.z; v.w += old.w;
            }
            if (RELUOUT) {
                v.x = fmaxf(v.x, 0.f); v.y = fmaxf(v.y, 0.f);
                v.z = fmaxf(v.z, 0.f); v.w = fmaxf(v.w, 0.f);
            }
            *(float4*)(dst + g * 4) = v;
        }
    }
}

// ---------------- launch ----------------------------------------------------------
extern "C" void kernel_launch(void* const* d_in, const int* in_sizes, int n_in,
                              void* d_out, int out_size) {
    const float* x       = (const float*)d_in[0];
    const float* w_shift = (const float*)d_in[1];
    const float* b_shift = (const float*)d_in[2];
    const float* conv_w  = (const float*)d_in[3];
    const float* conv_b  = (const float*)d_in[4];
    const float* res_b   = (const float*)d_in[6];
    const float* skip_b  = (const float*)d_in[8];
    const float* a_b     = (const float*)d_in[10];
    const float* b_b     = (const float*)d_in[12];
    const float* res_w   = (const float*)d_in[5];
    const float* skip_w  = (const float*)d_in[7];
    const float* a_w     = (const float*)d_in[9];
    const float* b_w     = (const float*)d_in[11];
    float* out = (float*)d_out;

    float *p_h, *p_gated, *p_skips, *p_z, *p_Aconv, *p_Ares, *p_Askip, *p_Aa, *p_Ab;
    cudaGetSymbolAddress((void**)&p_h, g_h);
    cudaGetSymbolAddress((void**)&p_gated, g_gated);
    cudaGetSymbolAddress((void**)&p_skips, g_skips);
    cudaGetSymbolAddress((void**)&p_z, g_z);
    cudaGetSymbolAddress((void**)&p_Aconv, g_Aconv);
    cudaGetSymbolAddress((void**)&p_Ares, g_Ares);
    cudaGetSymbolAddress((void**)&p_Askip, g_Askip);
    cudaGetSymbolAddress((void**)&p_Aa, g_Aa);
    cudaGetSymbolAddress((void**)&p_Ab, g_Ab);

    // weight prep (cheap; every call to keep launch deterministic)
    prep_conv_kernel<<<(LAYERS * 256 * 256 + 255) / 256, 256>>>(conv_w);
    prep_res_kernel<<<(LAYERS * 128 * 128 + 255) / 256, 256>>>(res_w);
    prep_skip_kernel<<<(LAYERS * 128 * 256 + 255) / 256, 256>>>(skip_w);
    prep_ab_kernel<<<(256 * 256 + 255) / 256, 256>>>(a_w, b_w);

    front_kernel<<<(NB * NCH * W + 255) / 256, 256>>>(x, w_shift, b_shift);

    dim3 gconv(W / TT, 1, NB);
    dim3 gres(W / 128, 1, NB);
    dim3 gskip(W / 128, 2, NB);

    for (int l = 0; l < LAYERS; l++) {
        int d = 1 << (l % 10);
        conv_glu_kernel<<<gconv, 512>>>(p_Aconv + l * 256 * 256, conv_b + l * 256, d);
        // h += res_w @ gated + res_b
        gemm_kernel<true, false, false><<<gres, 256>>>(
            p_Ares + l * 128 * 128, 128, 128, res_b + l * 128, p_gated, p_h);
        // skips (+)= skip_w @ gated + skip_b   (layer 0 initializes)
        if (l == 0) {
            gemm_kernel<false, false, false><<<gskip, 256>>>(
                p_Askip, 256, 128, skip_b, p_gated, p_skips);
        } else {
            gemm_kernel<true, false, false><<<gskip, 256>>>(
                p_Askip + l * 128 * 256, 256, 128, skip_b + l * 256, p_gated, p_skips);
        }
    }

    // z = relu(a_w @ relu(skips) + a_b)
    gemm_kernel<false, true, true><<<gskip, 256>>>(p_Aa, 256, 256, a_b, p_skips, p_z);
    // out = b_w @ z + b_b
    gemm_kernel<false, false, false><<<gskip, 256>>>(p_Ab, 256, 256, b_b, p_z, out);

    (void)in_sizes; (void)n_in; (void)out_size;
}